// round 4
// baseline (speedup 1.0000x reference)
#include <cuda_runtime.h>
#include <cstdint>

#define NROWS 16384
#define DDIM  32
#define HDIM  128
#define BK    32                 // K floats per stage -> 128B rows
#define BN    40                 // 32 msg cols + degree col(32) + 7 pad (tiles 3..4)
#define STAGES 8
#define NT    (NROWS / BK)       // 512
#define ABYTES (128 * 128)       // 16384
#define BBYTES (BN * 128)        // 5120
#define STAGE_BYTES (ABYTES + BBYTES)               // 21504 (multiple of 1024)
#define SMEM_TOTAL  (1024 + STAGES * STAGE_BYTES)   // 173056

// device scratch
__device__ float g_msgB[BN * NROWS];   // [col][k]; cols0-31 tf32 msg, col32=1, 33-39=0
__device__ float g_agg [NROWS * DDIM];

// ---------------- PTX helpers ----------------
__device__ __forceinline__ void cp16(uint32_t dst, const void* src) {
    asm volatile("cp.async.cg.shared.global [%0], [%1], 16;" :: "r"(dst), "l"(src) : "memory");
}
__device__ __forceinline__ float tf32_rna(float x) {
    uint32_t r;
    asm("cvt.rna.tf32.f32 %0, %1;" : "=r"(r) : "f"(x));
    return __uint_as_float(r);
}
__device__ __forceinline__ void ldsm_x4(uint32_t& r0, uint32_t& r1, uint32_t& r2, uint32_t& r3,
                                        uint32_t addr) {
    asm volatile("ldmatrix.sync.aligned.m8n8.x4.shared.b16 {%0,%1,%2,%3}, [%4];"
                 : "=r"(r0), "=r"(r1), "=r"(r2), "=r"(r3) : "r"(addr));
}
__device__ __forceinline__ void ldsm_x2(uint32_t& r0, uint32_t& r1, uint32_t addr) {
    asm volatile("ldmatrix.sync.aligned.m8n8.x2.shared.b16 {%0,%1}, [%2];"
                 : "=r"(r0), "=r"(r1) : "r"(addr));
}
__device__ __forceinline__ void mma_tf32(float* c, uint32_t a0, uint32_t a1,
                                         uint32_t a2, uint32_t a3,
                                         uint32_t b0, uint32_t b1) {
    asm volatile(
        "mma.sync.aligned.m16n8k8.row.col.f32.tf32.tf32.f32 "
        "{%0,%1,%2,%3}, {%4,%5,%6,%7}, {%8,%9}, {%0,%1,%2,%3};"
        : "+f"(c[0]), "+f"(c[1]), "+f"(c[2]), "+f"(c[3])
        : "r"(a0), "r"(a1), "r"(a2), "r"(a3), "r"(b0), "r"(b1));
}

// ==================== Kernel 1: message MLP (4 threads/row) ====================
__global__ __launch_bounds__(256) void msg_kernel(
    const float* __restrict__ states, const float* __restrict__ W1,
    const float* __restrict__ b1,     const float* __restrict__ W2,
    const float* __restrict__ b2)
{
    __shared__ float sW1[DDIM * HDIM];   // [j][h]
    __shared__ float sW2[HDIM * DDIM];   // [h][d]
    const int tid = threadIdx.x;
    for (int i = tid; i < DDIM * HDIM; i += 256) sW1[i] = W1[i];
    for (int i = tid; i < HDIM * DDIM; i += 256) sW2[i] = W2[i];
    __syncthreads();

    const int gt  = blockIdx.x * 256 + tid;
    const int row = gt >> 2;
    const int q   = gt & 3;          // hidden slice q*32..q*32+31

    float s[DDIM];
    const float4* sp = reinterpret_cast<const float4*>(states + (size_t)row * DDIM);
    #pragma unroll
    for (int j4 = 0; j4 < 8; j4++) {
        float4 v = sp[j4];
        s[4*j4+0] = v.x; s[4*j4+1] = v.y; s[4*j4+2] = v.z; s[4*j4+3] = v.w;
    }
    float hid[32];
    #pragma unroll
    for (int h4 = 0; h4 < 8; h4++) {
        float4 b = __ldg(reinterpret_cast<const float4*>(b1 + q * 32) + h4);
        hid[4*h4+0] = b.x; hid[4*h4+1] = b.y; hid[4*h4+2] = b.z; hid[4*h4+3] = b.w;
    }
    #pragma unroll
    for (int j = 0; j < DDIM; j++) {
        const float sj = s[j];
        #pragma unroll
        for (int h4 = 0; h4 < 8; h4++) {
            float4 w = *reinterpret_cast<const float4*>(&sW1[j * HDIM + q * 32 + 4 * h4]);
            hid[4*h4+0] += sj * w.x; hid[4*h4+1] += sj * w.y;
            hid[4*h4+2] += sj * w.z; hid[4*h4+3] += sj * w.w;
        }
    }
    float m[DDIM];
    #pragma unroll
    for (int d = 0; d < DDIM; d++) m[d] = 0.f;
    #pragma unroll
    for (int h = 0; h < 32; h++) {
        float r = fmaxf(hid[h], 0.f);
        #pragma unroll
        for (int d4 = 0; d4 < 8; d4++) {
            float4 w = *reinterpret_cast<const float4*>(&sW2[(q * 32 + h) * DDIM + 4 * d4]);
            m[4*d4+0] += r * w.x; m[4*d4+1] += r * w.y;
            m[4*d4+2] += r * w.z; m[4*d4+3] += r * w.w;
        }
    }
    // reduce across the 4 threads of this row (consecutive lanes)
    #pragma unroll
    for (int e = 0; e < DDIM; e++) {
        m[e] += __shfl_xor_sync(0xffffffffu, m[e], 1);
        m[e] += __shfl_xor_sync(0xffffffffu, m[e], 2);
    }
    #pragma unroll
    for (int e = 0; e < 8; e++) {
        int d = q * 8 + e;
        g_msgB[(size_t)d * NROWS + row] = tf32_rna(m[d] + __ldg(&b2[d]));
    }
    if (q == 0) {
        g_msgB[(size_t)32 * NROWS + row] = 1.0f;   // degree ones-column
        #pragma unroll
        for (int d = 33; d < BN; d++) g_msgB[(size_t)d * NROWS + row] = 0.0f;
    }
}

// ==================== Kernel 2: tf32 mma.sync aggregation (4x2 warp tile) ====================
__device__ __forceinline__ void fill_stage(const float* __restrict__ adj, size_t rowBase,
                                           int tile, uint32_t stage, int tid)
{
    const float* aSrc = adj + rowBase * NROWS + (size_t)tile * BK;
    #pragma unroll
    for (int i = 0; i < 4; i++) {                     // A: 1024 16B chunks
        int c = tid + 256 * i;
        int r = c >> 3, k4 = c & 7;
        uint32_t dst = stage + ((r * 8 + (k4 ^ (r & 7))) << 4);
        cp16(dst, aSrc + (size_t)r * NROWS + (k4 << 2));
    }
    {                                                 // B: 320 chunks (40 rows)
        int r = tid >> 3, k4 = tid & 7;
        uint32_t dst = stage + ABYTES + ((r * 8 + (k4 ^ (r & 7))) << 4);
        cp16(dst, g_msgB + (size_t)r * NROWS + (size_t)tile * BK + (k4 << 2));
        if (tid < 64) {
            int c = tid + 256;
            r = c >> 3; k4 = c & 7;
            dst = stage + ABYTES + ((r * 8 + (k4 ^ (r & 7))) << 4);
            cp16(dst, g_msgB + (size_t)r * NROWS + (size_t)tile * BK + (k4 << 2));
        }
    }
    asm volatile("cp.async.commit_group;" ::: "memory");
}

__global__ __launch_bounds__(256, 1) void agg_kernel(const float* __restrict__ adj)
{
    extern __shared__ char smem[];
    uint32_t sraw = (uint32_t)__cvta_generic_to_shared(smem);
    const uint32_t stage0 = (sraw + 1023u) & ~1023u;
    float* sdeg = reinterpret_cast<float*>(smem + (stage0 - sraw));  // reused post-loop

    const int tid  = threadIdx.x;
    const int wid  = tid >> 5;
    const int lane = tid & 31;
    const int wr   = wid & 3;        // warp-row: rows wr*32 .. wr*32+31
    const int wc   = wid >> 2;       // warp-col: 0 -> n-tiles 0..2, 1 -> n-tiles 3..4
    const size_t rowBase = (size_t)blockIdx.x * 128;

    const int jm = lane >> 3;        // x4 matrix index
    const int qm = lane & 7;
    const int hb = (lane >> 3) & 1;  // x2 half select

    float acc[2][3][4];
    #pragma unroll
    for (int mi = 0; mi < 2; mi++)
        #pragma unroll
        for (int t = 0; t < 3; t++)
            #pragma unroll
            for (int e = 0; e < 4; e++) acc[mi][t][e] = 0.f;

    for (int t = 0; t < STAGES - 1; t++)
        fill_stage(adj, rowBase, t, stage0 + t * STAGE_BYTES, tid);

    for (int kt = 0; kt < NT; kt++) {
        asm volatile("cp.async.wait_group %0;" :: "n"(STAGES - 2) : "memory");
        __syncthreads();

        const uint32_t sA = stage0 + (uint32_t)(kt & (STAGES - 1)) * STAGE_BYTES;
        const uint32_t sB = sA + ABYTES;

        #pragma unroll
        for (int s = 0; s < 4; s++) {
            const int ch  = 2 * s + (jm & 1);
            const int chx = 2 * s + hb;
            // A fragments: two m16 blocks
            uint32_t a[2][4];
            #pragma unroll
            for (int mi = 0; mi < 2; mi++) {
                const int arow = wr * 32 + mi * 16 + (jm >> 1) * 8 + qm;
                ldsm_x4(a[mi][0], a[mi][1], a[mi][2], a[mi][3],
                        sA + ((arow * 8 + (ch ^ (arow & 7))) << 4));
            }
            if (wc == 0) {
                uint32_t b[6];
                const int nr0 = (jm >> 1) * 8 + qm;          // g0: tiles 0,1
                ldsm_x4(b[0], b[1], b[2], b[3],
                        sB + ((nr0 * 8 + (ch ^ (nr0 & 7))) << 4));
                const int nr2 = 16 + qm;                      // tile 2
                ldsm_x2(b[4], b[5], sB + ((nr2 * 8 + (chx ^ (nr2 & 7))) << 4));
                #pragma unroll
                for (int mi = 0; mi < 2; mi++) {
                    mma_tf32(acc[mi][0], a[mi][0], a[mi][2], a[mi][1], a[mi][3], b[0], b[1]);
                    mma_tf32(acc[mi][1], a[mi][0], a[mi][2], a[mi][1], a[mi][3], b[2], b[3]);
                    mma_tf32(acc[mi][2], a[mi][0], a[mi][2], a[mi][1], a[mi][3], b[4], b[5]);
                }
            } else {
                uint32_t b[4];
                const int nr3 = 24 + qm;                      // tile 3 (cols 24-31)
                ldsm_x2(b[0], b[1], sB + ((nr3 * 8 + (chx ^ (nr3 & 7))) << 4));
                const int nr4 = 32 + qm;                      // tile 4 (degree col 32)
                ldsm_x2(b[2], b[3], sB + ((nr4 * 8 + (chx ^ (nr4 & 7))) << 4));
                #pragma unroll
                for (int mi = 0; mi < 2; mi++) {
                    mma_tf32(acc[mi][0], a[mi][0], a[mi][2], a[mi][1], a[mi][3], b[0], b[1]);
                    mma_tf32(acc[mi][1], a[mi][0], a[mi][2], a[mi][1], a[mi][3], b[2], b[3]);
                }
            }
        }

        const int nxt = kt + STAGES - 1;
        if (nxt < NT)
            fill_stage(adj, rowBase, nxt, stage0 + (uint32_t)(nxt & (STAGES - 1)) * STAGE_BYTES, tid);
    }
    asm volatile("cp.async.wait_group 0;" ::: "memory");
    __syncthreads();

    // degree exchange: wc1 holds col32 in acc[mi][1], col offset 0 -> lanes lane%4==0
    if (wc == 1 && (lane & 3) == 0) {
        #pragma unroll
        for (int mi = 0; mi < 2; mi++) {
            int r0 = wr * 32 + mi * 16 + (lane >> 2);
            sdeg[r0]     = acc[mi][1][0];
            sdeg[r0 + 8] = acc[mi][1][2];
        }
    }
    __syncthreads();

    #pragma unroll
    for (int mi = 0; mi < 2; mi++) {
        const int r0 = wr * 32 + mi * 16 + (lane >> 2);
        const int r1 = r0 + 8;
        const float rd0 = 1.0f / fmaxf(sdeg[r0], 1.0f);
        const float rd1 = 1.0f / fmaxf(sdeg[r1], 1.0f);
        const int ntl = (wc == 0) ? 3 : 1;
        #pragma unroll
        for (int t = 0; t < 3; t++) {
            if (t >= ntl) break;
            const int colb = (wc == 0 ? t * 8 : 24) + 2 * (lane & 3);
            float2 olo = {acc[mi][t][0] * rd0, acc[mi][t][1] * rd0};
            float2 ohi = {acc[mi][t][2] * rd1, acc[mi][t][3] * rd1};
            *reinterpret_cast<float2*>(&g_agg[(rowBase + r0) * DDIM + colb]) = olo;
            *reinterpret_cast<float2*>(&g_agg[(rowBase + r1) * DDIM + colb]) = ohi;
        }
    }
}

// ==================== Kernel 3: update MLP (4 threads/row) ====================
__global__ __launch_bounds__(256) void upd_kernel(
    const float* __restrict__ states, const float* __restrict__ W1,
    const float* __restrict__ b1,     const float* __restrict__ W2,
    const float* __restrict__ b2,     float* __restrict__ out)
{
    __shared__ float sW1[2 * DDIM * HDIM];  // [j][h] 32KB
    __shared__ float sW2[HDIM * DDIM];      // [h][d] 16KB
    const int tid = threadIdx.x;
    for (int i = tid; i < 2 * DDIM * HDIM; i += 256) sW1[i] = W1[i];
    for (int i = tid; i < HDIM * DDIM; i += 256)     sW2[i] = W2[i];
    __syncthreads();

    const int gt  = blockIdx.x * 256 + tid;
    const int row = gt >> 2;
    const int q   = gt & 3;

    float x[2 * DDIM];
    const float4* sp = reinterpret_cast<const float4*>(states + (size_t)row * DDIM);
    const float4* gp = reinterpret_cast<const float4*>(g_agg  + (size_t)row * DDIM);
    #pragma unroll
    for (int j4 = 0; j4 < 8; j4++) {
        float4 v = sp[j4];
        x[4*j4+0] = v.x; x[4*j4+1] = v.y; x[4*j4+2] = v.z; x[4*j4+3] = v.w;
        float4 g = gp[j4];
        x[DDIM+4*j4+0] = g.x; x[DDIM+4*j4+1] = g.y;
        x[DDIM+4*j4+2] = g.z; x[DDIM+4*j4+3] = g.w;
    }
    float hid[32];
    #pragma unroll
    for (int h4 = 0; h4 < 8; h4++) {
        float4 b = __ldg(reinterpret_cast<const float4*>(b1 + q * 32) + h4);
        hid[4*h4+0] = b.x; hid[4*h4+1] = b.y; hid[4*h4+2] = b.z; hid[4*h4+3] = b.w;
    }
    #pragma unroll
    for (int j = 0; j < 2 * DDIM; j++) {
        const float xj = x[j];
        #pragma unroll
        for (int h4 = 0; h4 < 8; h4++) {
            float4 w = *reinterpret_cast<const float4*>(&sW1[j * HDIM + q * 32 + 4 * h4]);
            hid[4*h4+0] += xj * w.x; hid[4*h4+1] += xj * w.y;
            hid[4*h4+2] += xj * w.z; hid[4*h4+3] += xj * w.w;
        }
    }
    float m[DDIM];
    #pragma unroll
    for (int d = 0; d < DDIM; d++) m[d] = 0.f;
    #pragma unroll
    for (int h = 0; h < 32; h++) {
        float r = fmaxf(hid[h], 0.f);
        #pragma unroll
        for (int d4 = 0; d4 < 8; d4++) {
            float4 w = *reinterpret_cast<const float4*>(&sW2[(q * 32 + h) * DDIM + 4 * d4]);
            m[4*d4+0] += r * w.x; m[4*d4+1] += r * w.y;
            m[4*d4+2] += r * w.z; m[4*d4+3] += r * w.w;
        }
    }
    #pragma unroll
    for (int e = 0; e < DDIM; e++) {
        m[e] += __shfl_xor_sync(0xffffffffu, m[e], 1);
        m[e] += __shfl_xor_sync(0xffffffffu, m[e], 2);
    }
    float4 o0, o1;
    const float4 bb0 = __ldg(reinterpret_cast<const float4*>(b2 + q * 8));
    const float4 bb1 = __ldg(reinterpret_cast<const float4*>(b2 + q * 8) + 1);
    o0.x = m[q*8+0] + bb0.x; o0.y = m[q*8+1] + bb0.y;
    o0.z = m[q*8+2] + bb0.z; o0.w = m[q*8+3] + bb0.w;
    o1.x = m[q*8+4] + bb1.x; o1.y = m[q*8+5] + bb1.y;
    o1.z = m[q*8+6] + bb1.z; o1.w = m[q*8+7] + bb1.w;
    float4* op = reinterpret_cast<float4*>(out + (size_t)row * DDIM + q * 8);
    op[0] = o0; op[1] = o1;
}

// ==================== launch ====================
extern "C" void kernel_launch(void* const* d_in, const int* in_sizes, int n_in,
                              void* d_out, int out_size)
{
    const float* states = (const float*)d_in[0];
    const float* adj    = (const float*)d_in[1];
    const float* mW1    = (const float*)d_in[2];
    const float* mb1    = (const float*)d_in[3];
    const float* mW2    = (const float*)d_in[4];
    const float* mb2    = (const float*)d_in[5];
    const float* uW1    = (const float*)d_in[6];
    const float* ub1    = (const float*)d_in[7];
    const float* uW2    = (const float*)d_in[8];
    const float* ub2    = (const float*)d_in[9];
    float* out = (float*)d_out;

    cudaFuncSetAttribute(agg_kernel, cudaFuncAttributeMaxDynamicSharedMemorySize, SMEM_TOTAL);

    msg_kernel<<<NROWS * 4 / 256, 256>>>(states, mW1, mb1, mW2, mb2);
    agg_kernel<<<NROWS / 128, 256, SMEM_TOTAL>>>(adj);
    upd_kernel<<<NROWS * 4 / 256, 256>>>(states, uW1, ub1, uW2, ub2, out);
}

// round 5
// speedup vs baseline: 1.7927x; 1.7927x over previous
#include <cuda_runtime.h>
#include <cstdint>

#define NROWS 16384
#define DDIM  32
#define HDIM  128
#define BK    32                 // K floats per stage -> 128B rows
#define BN    40                 // 32 msg cols + degree(col32) + 7 pad -> 5 live n8-tiles
#define STAGES 8
#define NT    (NROWS / BK)       // 512
#define ABYTES (128 * 128)       // 16384
#define BBYTES (BN * 128)        // 5120
#define STAGE_BYTES (ABYTES + BBYTES)               // 21504
#define SMEM_TOTAL  (1024 + STAGES * STAGE_BYTES)   // 173056

// device scratch
__device__ float g_msgB[BN * NROWS];   // [col][k]; cols0-31 tf32 msg, col32=1, 33-39=0
__device__ float g_agg [NROWS * DDIM];

// ---------------- PTX helpers ----------------
__device__ __forceinline__ void cp16(uint32_t dst, const void* src) {
    asm volatile("cp.async.cg.shared.global [%0], [%1], 16;" :: "r"(dst), "l"(src) : "memory");
}
__device__ __forceinline__ float tf32_rna(float x) {
    uint32_t r;
    asm("cvt.rna.tf32.f32 %0, %1;" : "=r"(r) : "f"(x));
    return __uint_as_float(r);
}
__device__ __forceinline__ void ldsm_x4(uint32_t& r0, uint32_t& r1, uint32_t& r2, uint32_t& r3,
                                        uint32_t addr) {
    asm volatile("ldmatrix.sync.aligned.m8n8.x4.shared.b16 {%0,%1,%2,%3}, [%4];"
                 : "=r"(r0), "=r"(r1), "=r"(r2), "=r"(r3) : "r"(addr));
}
__device__ __forceinline__ void ldsm_x2(uint32_t& r0, uint32_t& r1, uint32_t addr) {
    asm volatile("ldmatrix.sync.aligned.m8n8.x2.shared.b16 {%0,%1}, [%2];"
                 : "=r"(r0), "=r"(r1) : "r"(addr));
}
__device__ __forceinline__ void mma_tf32(float* c, uint32_t a0, uint32_t a1,
                                         uint32_t a2, uint32_t a3,
                                         uint32_t b0, uint32_t b1) {
    asm volatile(
        "mma.sync.aligned.m16n8k8.row.col.f32.tf32.tf32.f32 "
        "{%0,%1,%2,%3}, {%4,%5,%6,%7}, {%8,%9}, {%0,%1,%2,%3};"
        : "+f"(c[0]), "+f"(c[1]), "+f"(c[2]), "+f"(c[3])
        : "r"(a0), "r"(a1), "r"(a2), "r"(a3), "r"(b0), "r"(b1));
}

// ==================== Kernel 1: message MLP (round-3 proven shape) ====================
__global__ __launch_bounds__(128) void msg_kernel(
    const float* __restrict__ states, const float* __restrict__ W1,
    const float* __restrict__ b1,     const float* __restrict__ W2,
    const float* __restrict__ b2)
{
    __shared__ float sW1[DDIM * HDIM];
    __shared__ float sW2[HDIM * DDIM];
    const int tid = threadIdx.x;
    for (int i = tid; i < DDIM * HDIM; i += 128) sW1[i] = W1[i];
    for (int i = tid; i < HDIM * DDIM; i += 128) sW2[i] = W2[i];
    __syncthreads();

    const int row = blockIdx.x * 128 + tid;
    float s[DDIM];
    const float4* sp = reinterpret_cast<const float4*>(states + (size_t)row * DDIM);
    #pragma unroll
    for (int j4 = 0; j4 < DDIM / 4; j4++) {
        float4 v = sp[j4];
        s[4*j4+0] = v.x; s[4*j4+1] = v.y; s[4*j4+2] = v.z; s[4*j4+3] = v.w;
    }
    float m[DDIM];
    #pragma unroll
    for (int d = 0; d < DDIM; d++) m[d] = __ldg(&b2[d]);

    #pragma unroll 2
    for (int hg = 0; hg < HDIM / 4; hg++) {
        float4 hid = __ldg(reinterpret_cast<const float4*>(b1) + hg);
        #pragma unroll
        for (int j = 0; j < DDIM; j++) {
            float4 w = *reinterpret_cast<const float4*>(&sW1[j * HDIM + 4 * hg]);
            hid.x += s[j] * w.x; hid.y += s[j] * w.y;
            hid.z += s[j] * w.z; hid.w += s[j] * w.w;
        }
        float rr[4] = {fmaxf(hid.x, 0.f), fmaxf(hid.y, 0.f),
                       fmaxf(hid.z, 0.f), fmaxf(hid.w, 0.f)};
        #pragma unroll
        for (int e = 0; e < 4; e++) {
            float r = rr[e];
            #pragma unroll
            for (int d4 = 0; d4 < DDIM / 4; d4++) {
                float4 w = *reinterpret_cast<const float4*>(&sW2[(4*hg+e) * DDIM + 4*d4]);
                m[4*d4+0] += r * w.x; m[4*d4+1] += r * w.y;
                m[4*d4+2] += r * w.z; m[4*d4+3] += r * w.w;
            }
        }
    }
    #pragma unroll
    for (int d = 0; d < DDIM; d++)
        g_msgB[(size_t)d * NROWS + row] = tf32_rna(m[d]);
    g_msgB[(size_t)32 * NROWS + row] = 1.0f;          // degree column
    #pragma unroll
    for (int d = 33; d < BN; d++)
        g_msgB[(size_t)d * NROWS + row] = 0.0f;       // pad
}

// ==================== Kernel 2: tf32 mma.sync aggregation (4 warps x 32 rows) ====================
__device__ __forceinline__ void fill_stage(const float* __restrict__ adj, size_t rowBase,
                                           int tile, uint32_t stage, int tid)
{
    const float* aSrc = adj + rowBase * NROWS + (size_t)tile * BK;
    #pragma unroll
    for (int i = 0; i < 8; i++) {                     // A: 1024 16B chunks / 128 thr
        int c = tid + 128 * i;
        int r = c >> 3, k4 = c & 7;
        uint32_t dst = stage + ((r * 8 + (k4 ^ (r & 7))) << 4);
        cp16(dst, aSrc + (size_t)r * NROWS + (k4 << 2));
    }
    #pragma unroll
    for (int i = 0; i < 3; i++) {                     // B: 320 chunks
        int c = tid + 128 * i;
        if (i < 2 || c < BN * 8) {
            int r = c >> 3, k4 = c & 7;
            uint32_t dst = stage + ABYTES + ((r * 8 + (k4 ^ (r & 7))) << 4);
            cp16(dst, g_msgB + (size_t)r * NROWS + (size_t)tile * BK + (k4 << 2));
        }
    }
    asm volatile("cp.async.commit_group;" ::: "memory");
}

__global__ __launch_bounds__(128, 1) void agg_kernel(const float* __restrict__ adj)
{
    extern __shared__ char smem[];
    uint32_t sraw = (uint32_t)__cvta_generic_to_shared(smem);
    const uint32_t stage0 = (sraw + 1023u) & ~1023u;

    const int tid  = threadIdx.x;
    const int wid  = tid >> 5;       // warp-row: rows wid*32 .. wid*32+31
    const int lane = tid & 31;
    const size_t rowBase = (size_t)blockIdx.x * 128;

    const int jm = lane >> 3;        // x4 matrix index 0..3
    const int qm = lane & 7;
    const int hb = jm & 1;           // x2 half select (lanes 0-15 relevant)

    float acc[2][5][4];              // [m16 block][n-tile][frag]
    #pragma unroll
    for (int mi = 0; mi < 2; mi++)
        #pragma unroll
        for (int t = 0; t < 5; t++)
            #pragma unroll
            for (int e = 0; e < 4; e++) acc[mi][t][e] = 0.f;

    for (int t = 0; t < STAGES - 1; t++)
        fill_stage(adj, rowBase, t, stage0 + t * STAGE_BYTES, tid);

    for (int kt = 0; kt < NT; kt++) {
        asm volatile("cp.async.wait_group %0;" :: "n"(STAGES - 2) : "memory");
        __syncthreads();

        const uint32_t sA = stage0 + (uint32_t)(kt & (STAGES - 1)) * STAGE_BYTES;
        const uint32_t sB = sA + ABYTES;

        #pragma unroll
        for (int s = 0; s < 4; s++) {
            const int ch  = 2 * s + (jm & 1);
            const int chx = 2 * s + hb;
            // B fragments: tiles 0..3 via two x4 loads, tile 4 (degree) via x2
            uint32_t b[10];
            {
                const int nr0 = (jm >> 1) * 8 + qm;            // rows 0..15 -> tiles 0,1
                ldsm_x4(b[0], b[1], b[2], b[3],
                        sB + ((nr0 * 8 + (ch ^ (nr0 & 7))) << 4));
                const int nr1 = 16 + (jm >> 1) * 8 + qm;        // rows 16..31 -> tiles 2,3
                ldsm_x4(b[4], b[5], b[6], b[7],
                        sB + ((nr1 * 8 + (ch ^ (nr1 & 7))) << 4));
                const int nr2 = 32 + qm;                        // rows 32..39 -> tile 4
                ldsm_x2(b[8], b[9], sB + ((nr2 * 8 + (chx ^ (nr2 & 7))) << 4));
            }
            #pragma unroll
            for (int mi = 0; mi < 2; mi++) {
                const int arow = wid * 32 + mi * 16 + (jm >> 1) * 8 + qm;
                uint32_t a0, a1, a2, a3;
                ldsm_x4(a0, a1, a2, a3, sA + ((arow * 8 + (ch ^ (arow & 7))) << 4));
                #pragma unroll
                for (int t = 0; t < 5; t++)
                    mma_tf32(acc[mi][t], a0, a2, a1, a3, b[2*t], b[2*t+1]);
            }
        }

        const int nxt = kt + STAGES - 1;
        if (nxt < NT)
            fill_stage(adj, rowBase, nxt, stage0 + (uint32_t)(nxt & (STAGES - 1)) * STAGE_BYTES, tid);
    }
    asm volatile("cp.async.wait_group 0;" ::: "memory");

    // degree: tile 4 col offset 0 -> lanes lane%4==0 hold col 32 (elems 0 and 2)
    const int srcLane = lane & ~3;
    #pragma unroll
    for (int mi = 0; mi < 2; mi++) {
        float dlo = __shfl_sync(0xffffffffu, acc[mi][4][0], srcLane);
        float dhi = __shfl_sync(0xffffffffu, acc[mi][4][2], srcLane);
        float rd0 = 1.0f / fmaxf(dlo, 1.0f);
        float rd1 = 1.0f / fmaxf(dhi, 1.0f);
        const size_t r0 = rowBase + (size_t)(wid * 32 + mi * 16 + (lane >> 2));
        const size_t r1 = r0 + 8;
        #pragma unroll
        for (int t = 0; t < 4; t++) {
            const int colb = t * 8 + 2 * (lane & 3);
            float2 olo = {acc[mi][t][0] * rd0, acc[mi][t][1] * rd0};
            float2 ohi = {acc[mi][t][2] * rd1, acc[mi][t][3] * rd1};
            *reinterpret_cast<float2*>(&g_agg[r0 * DDIM + colb]) = olo;
            *reinterpret_cast<float2*>(&g_agg[r1 * DDIM + colb]) = ohi;
        }
    }
}

// ==================== Kernel 3: update MLP (round-3 proven shape) ====================
__global__ __launch_bounds__(128) void upd_kernel(
    const float* __restrict__ states, const float* __restrict__ W1,
    const float* __restrict__ b1,     const float* __restrict__ W2,
    const float* __restrict__ b2,     float* __restrict__ out)
{
    __shared__ float sW1[2 * DDIM * HDIM];
    __shared__ float sW2[HDIM * DDIM];
    const int tid = threadIdx.x;
    for (int i = tid; i < 2 * DDIM * HDIM; i += 128) sW1[i] = W1[i];
    for (int i = tid; i < HDIM * DDIM; i += 128)     sW2[i] = W2[i];
    __syncthreads();

    const int row = blockIdx.x * 128 + tid;
    float x[2 * DDIM];
    const float4* sp = reinterpret_cast<const float4*>(states + (size_t)row * DDIM);
    const float4* gp = reinterpret_cast<const float4*>(g_agg  + (size_t)row * DDIM);
    #pragma unroll
    for (int j4 = 0; j4 < DDIM / 4; j4++) {
        float4 v = sp[j4];
        x[4*j4+0] = v.x; x[4*j4+1] = v.y; x[4*j4+2] = v.z; x[4*j4+3] = v.w;
        float4 g = gp[j4];
        x[DDIM+4*j4+0] = g.x; x[DDIM+4*j4+1] = g.y;
        x[DDIM+4*j4+2] = g.z; x[DDIM+4*j4+3] = g.w;
    }
    float m[DDIM];
    #pragma unroll
    for (int d = 0; d < DDIM; d++) m[d] = __ldg(&b2[d]);

    #pragma unroll 2
    for (int hg = 0; hg < HDIM / 4; hg++) {
        float4 hid = __ldg(reinterpret_cast<const float4*>(b1) + hg);
        #pragma unroll
        for (int j = 0; j < 2 * DDIM; j++) {
            float4 w = *reinterpret_cast<const float4*>(&sW1[j * HDIM + 4 * hg]);
            hid.x += x[j] * w.x; hid.y += x[j] * w.y;
            hid.z += x[j] * w.z; hid.w += x[j] * w.w;
        }
        float rr[4] = {fmaxf(hid.x, 0.f), fmaxf(hid.y, 0.f),
                       fmaxf(hid.z, 0.f), fmaxf(hid.w, 0.f)};
        #pragma unroll
        for (int e = 0; e < 4; e++) {
            float r = rr[e];
            #pragma unroll
            for (int d4 = 0; d4 < DDIM / 4; d4++) {
                float4 w = *reinterpret_cast<const float4*>(&sW2[(4*hg+e) * DDIM + 4*d4]);
                m[4*d4+0] += r * w.x; m[4*d4+1] += r * w.y;
                m[4*d4+2] += r * w.z; m[4*d4+3] += r * w.w;
            }
        }
    }
    float4* op = reinterpret_cast<float4*>(out + (size_t)row * DDIM);
    #pragma unroll
    for (int d4 = 0; d4 < DDIM / 4; d4++) {
        float4 o;
        o.x = m[4*d4+0]; o.y = m[4*d4+1]; o.z = m[4*d4+2]; o.w = m[4*d4+3];
        op[d4] = o;
    }
}

// ==================== launch ====================
extern "C" void kernel_launch(void* const* d_in, const int* in_sizes, int n_in,
                              void* d_out, int out_size)
{
    const float* states = (const float*)d_in[0];
    const float* adj    = (const float*)d_in[1];
    const float* mW1    = (const float*)d_in[2];
    const float* mb1    = (const float*)d_in[3];
    const float* mW2    = (const float*)d_in[4];
    const float* mb2    = (const float*)d_in[5];
    const float* uW1    = (const float*)d_in[6];
    const float* ub1    = (const float*)d_in[7];
    const float* uW2    = (const float*)d_in[8];
    const float* ub2    = (const float*)d_in[9];
    float* out = (float*)d_out;

    cudaFuncSetAttribute(agg_kernel, cudaFuncAttributeMaxDynamicSharedMemorySize, SMEM_TOTAL);

    msg_kernel<<<NROWS / 128, 128>>>(states, mW1, mb1, mW2, mb2);
    agg_kernel<<<NROWS / 128, 128, SMEM_TOTAL>>>(adj);
    upd_kernel<<<NROWS / 128, 128>>>(states, uW1, ub1, uW2, ub2, out);
}